// round 14
// baseline (speedup 1.0000x reference)
#include <cuda_runtime.h>
#include <cuda_fp16.h>
#include <cstdint>

#define NUM_USERS 100000
#define NUM_ITEMS 200000
#define NN (NUM_USERS + NUM_ITEMS)   // 300000
#define EE 2000000
#define DD 64
#define TOT (NN * DD)                // 19,200,000
#define TOT8 (TOT / 8)
#define U8  (NUM_USERS * DD / 8)

#define SCAN_TILE 4096               // 256 threads x 16 items
#define NTILES ((NN + SCAN_TILE - 1) / SCAN_TILE)   // 74 (< 148 SMs: co-resident)
#define NBUCKET 64
#define NPAIR (NN / 2)               // 150000 row pairs

// ---- allocation-free scratch -----------------------------------------------
__device__ __half g_h0[TOT];       // ego in fp16
__device__ __half g_bufA[TOT];     // h1
__device__ __half g_bufB[TOT];     // h2
__device__ int    g_cnt[NN];       // histogram -> scatter cursor (zero-init; re-zeroed each call)
__device__ int    g_rowptr[NN + 1];
__device__ unsigned long long g_tile_state[NTILES];  // lookback state; 0=invalid
__device__ int    g_dhist[NBUCKET];            // degree histogram -> global bases
__device__ int    g_bhist[NTILES * NBUCKET];   // per-tile bucket histograms
__device__ int    g_perm[NN];        // rows sorted by degree (descending)
__device__ int    g_scan_done;       // ticket for last-block bucket scan
__device__ int2   g_edges[EE];       // (col, val bits) sorted by row

__device__ __forceinline__ uint32_t h2u(__half2 h) { return *reinterpret_cast<uint32_t*>(&h); }
__device__ __forceinline__ __half2  u2h(uint32_t u) { return *reinterpret_cast<__half2*>(&u); }

// ---------------------------------------------------------------------------
// conv_hist: g_h0 = fp16(concat(ue, ie))  AND  g_cnt[r]++ per edge.
// ---------------------------------------------------------------------------
__global__ void __launch_bounds__(256) conv_hist_kernel(const float4* __restrict__ ue,
                                                        const float4* __restrict__ ie,
                                                        const int* __restrict__ rows) {
    int i = blockIdx.x * blockDim.x + threadIdx.x;
    if (i < EE) atomicAdd(&g_cnt[__ldcs(&rows[i])], 1);
    if (i >= TOT8) return;
    float4 f0, f1;
    if (i < U8) {
        f0 = __ldg(&ue[2 * i]);        f1 = __ldg(&ue[2 * i + 1]);
    } else {
        f0 = __ldg(&ie[2 * (i - U8)]); f1 = __ldg(&ie[2 * (i - U8) + 1]);
    }
    uint4 h;
    h.x = h2u(__float22half2_rn(make_float2(f0.x, f0.y)));
    h.y = h2u(__float22half2_rn(make_float2(f0.z, f0.w)));
    h.z = h2u(__float22half2_rn(make_float2(f1.x, f1.y)));
    h.w = h2u(__float22half2_rn(make_float2(f1.z, f1.w)));
    reinterpret_cast<uint4*>(g_h0)[i] = h;
}

// ---------------------------------------------------------------------------
// Single-pass decoupled-lookback scan + degree histogram + (last block)
// descending bucket-base scan.
// ---------------------------------------------------------------------------
__global__ void __launch_bounds__(256) scan_lookback_kernel() {
    __shared__ int s_warp[8];
    __shared__ int s_total;
    __shared__ uint32_t s_prefix;
    __shared__ int s_hist[NBUCKET];
    __shared__ int s_ticket;
    int tid = threadIdx.x;
    int blk = blockIdx.x;
    int base = blk * SCAN_TILE + tid * 16;
    if (tid < NBUCKET) s_hist[tid] = 0;

    int v[16];
    #pragma unroll
    for (int j = 0; j < 4; j++) {
        int idx = base + j * 4;
        if (idx + 3 < NN) {
            int4 t4 = *reinterpret_cast<const int4*>(&g_cnt[idx]);
            v[j*4] = t4.x; v[j*4+1] = t4.y; v[j*4+2] = t4.z; v[j*4+3] = t4.w;
        } else {
            v[j*4]   = (idx     < NN) ? g_cnt[idx]     : 0;
            v[j*4+1] = (idx + 1 < NN) ? g_cnt[idx + 1] : 0;
            v[j*4+2] = (idx + 2 < NN) ? g_cnt[idx + 2] : 0;
            v[j*4+3] = (idx + 3 < NN) ? g_cnt[idx + 3] : 0;
        }
    }
    int tsum = 0;
    #pragma unroll
    for (int j = 0; j < 16; j++) tsum += v[j];

    int lane = tid & 31, wid = tid >> 5;
    int x = tsum;
    #pragma unroll
    for (int d = 1; d < 32; d <<= 1) {
        int y = __shfl_up_sync(0xffffffffu, x, d);
        if (lane >= d) x += y;
    }
    if (lane == 31) s_warp[wid] = x;
    __syncthreads();

    #pragma unroll
    for (int j = 0; j < 16; j++) {
        if (base + j < NN) atomicAdd(&s_hist[v[j] < NBUCKET - 1 ? v[j] : NBUCKET - 1], 1);
    }

    if (wid == 0) {
        int w = (lane < 8) ? s_warp[lane] : 0;
        #pragma unroll
        for (int d = 1; d < 8; d <<= 1) {
            int y = __shfl_up_sync(0xffffffffu, w, d);
            if (lane >= d) w += y;
        }
        if (lane < 8) s_warp[lane] = w;
    }
    __syncthreads();
    int woff = (wid > 0) ? s_warp[wid - 1] : 0;
    int texcl = woff + x - tsum;
    if (tid == 255) s_total = woff + x;
    if (tid < NBUCKET) {
        int h = s_hist[tid];
        g_bhist[blk * NBUCKET + tid] = h;
        if (h) atomicAdd(&g_dhist[tid], h);
    }
    __syncthreads();

    if (tid < 32) {
        if (blk == 0) {
            if (lane == 0) {
                s_prefix = 0;
                *(volatile unsigned long long*)&g_tile_state[0] =
                    (2ULL << 32) | (uint32_t)s_total;
            }
        } else {
            if (lane == 0)
                *(volatile unsigned long long*)&g_tile_state[blk] =
                    (1ULL << 32) | (uint32_t)s_total;
            unsigned long long prefix = 0;
            int b2 = blk - 1;
            while (true) {
                int p = b2 - lane;
                unsigned long long s;
                if (p < 0) {
                    s = (2ULL << 32);
                } else {
                    do { s = *(volatile unsigned long long*)&g_tile_state[p]; } while (s == 0ULL);
                }
                uint32_t st  = (uint32_t)(s >> 32);
                uint32_t val = (uint32_t)s;
                unsigned m = __ballot_sync(0xffffffffu, st == 2u);
                if (m) {
                    int k = __ffs(m) - 1;
                    prefix += __reduce_add_sync(0xffffffffu, (lane <= k) ? val : 0u);
                    break;
                }
                prefix += __reduce_add_sync(0xffffffffu, val);
                b2 -= 32;
            }
            if (lane == 0) {
                s_prefix = (uint32_t)prefix;
                *(volatile unsigned long long*)&g_tile_state[blk] =
                    (2ULL << 32) | (uint32_t)(prefix + (uint32_t)s_total);
            }
        }
    }
    __syncthreads();

    int g = (int)s_prefix + texcl;
    #pragma unroll
    for (int j = 0; j < 16; j++) {
        int idx = base + j;
        if (idx < NN) {
            g_cnt[idx] = g;
            g_rowptr[idx + 1] = g + v[j];
            g += v[j];
        }
    }
    if (blk == 0 && tid == 0) g_rowptr[0] = 0;

    __threadfence();
    __syncthreads();
    if (tid == 0) s_ticket = atomicAdd(&g_scan_done, 1);
    __syncthreads();
    if (s_ticket == NTILES - 1 && tid < 32) {
        __threadfence();
        int l = tid;
        int a = g_dhist[63 - l];
        int b = g_dhist[31 - l];
        int xa = a, xb = b;
        #pragma unroll
        for (int d = 1; d < 32; d <<= 1) {
            int ya = __shfl_up_sync(0xffffffffu, xa, d);
            int yb = __shfl_up_sync(0xffffffffu, xb, d);
            if (l >= d) { xa += ya; xb += yb; }
        }
        int totalA = __shfl_sync(0xffffffffu, xa, 31);
        g_dhist[63 - l] = xa - a;
        g_dhist[31 - l] = totalA + xb - b;
        if (l == 0) g_scan_done = 0;
    }
}

// ---------------------------------------------------------------------------
// scatter: edges into row buckets; blocks 0..NTILES-1 also build the
// degree-sorted perm for their row tile.
// ---------------------------------------------------------------------------
__global__ void __launch_bounds__(256) scatter_kernel(const int* __restrict__ rows,
                                                      const int* __restrict__ cols,
                                                      const float* __restrict__ vals) {
    __shared__ int s_off[NBUCKET];
    int tid = threadIdx.x;
    int blk = blockIdx.x;

    if (blk < NTILES) {
        int b = tid >> 2, q = tid & 3;
        int per = (blk + 3) >> 2;
        int p0 = q * per;
        int p1 = (blk < p0 + per) ? blk : p0 + per;
        int sum = 0;
        for (int p = p0; p < p1; p++) sum += __ldg(&g_bhist[p * NBUCKET + b]);
        sum += __shfl_xor_sync(0xffffffffu, sum, 1);
        sum += __shfl_xor_sync(0xffffffffu, sum, 2);
        if (q == 0) s_off[b] = __ldg(&g_dhist[b]) + sum;
        __syncthreads();
        int base = blk * SCAN_TILE + tid * 16;
        #pragma unroll
        for (int j = 0; j < 16; j++) {
            int idx = base + j;
            if (idx < NN) {
                int deg = __ldg(&g_rowptr[idx + 1]) - __ldg(&g_rowptr[idx]);
                int bb = deg < NBUCKET - 1 ? deg : NBUCKET - 1;
                int pos = atomicAdd(&s_off[bb], 1);
                g_perm[pos] = idx;
            }
        }
    }

    int e = blk * blockDim.x + tid;
    if (e >= EE) return;
    int r = __ldcs(&rows[e]);
    int c = __ldcs(&cols[e]);
    float v = __ldcs(&vals[e]);
    int pos = atomicAdd(&g_cnt[r], 1);
    g_edges[pos] = make_int2(c, __float_as_int(v));
}

// ---------------------------------------------------------------------------
// one edge accumulation (16B chunk)
// ---------------------------------------------------------------------------
__device__ __forceinline__ void edge_acc(int2 ev, const __half* __restrict__ src, int ch,
                                         float2& a0, float2& a1, float2& a2, float2& a3) {
    float v = __int_as_float(ev.y);
    uint4 x = __ldg(reinterpret_cast<const uint4*>(src + (size_t)ev.x * DD + ch));
    float2 f0 = __half22float2(u2h(x.x));
    float2 f1 = __half22float2(u2h(x.y));
    float2 f2 = __half22float2(u2h(x.z));
    float2 f3 = __half22float2(u2h(x.w));
    a0.x += v * f0.x; a0.y += v * f0.y;
    a1.x += v * f1.x; a1.y += v * f1.y;
    a2.x += v * f2.x; a2.y += v * f2.y;
    a3.x += v * f3.x; a3.y += v * f3.y;
}

// ---------------------------------------------------------------------------
// Paired CSR accumulation: two rows (adjacent in degree-sorted perm, so
// near-equal degree) processed with interleaved iterations -> 2 independent
// gather chains per thread (double MLP). 8 threads per row-pair chunk.
// ---------------------------------------------------------------------------
__device__ __forceinline__ void csr_accum_pair(
    int rowA, int rowB, int ch, const __half* __restrict__ src,
    float2& a0, float2& a1, float2& a2, float2& a3,
    float2& b0, float2& b1, float2& b2, float2& b3) {
    int eA   = __ldg(&g_rowptr[rowA]);
    int endA = __ldg(&g_rowptr[rowA + 1]);
    int eB   = __ldg(&g_rowptr[rowB]);
    int endB = __ldg(&g_rowptr[rowB + 1]);
    a0 = make_float2(0.f, 0.f); a1 = a0; a2 = a0; a3 = a0;
    b0 = a0; b1 = a0; b2 = a0; b3 = a0;
    int dA = endA - eA, dB = endB - eB;
    int nmin = dA < dB ? dA : dB;
    #pragma unroll 2
    for (int k = 0; k < nmin; k++) {
        int2 evA = __ldg(&g_edges[eA + k]);
        int2 evB = __ldg(&g_edges[eB + k]);
        edge_acc(evA, src, ch, a0, a1, a2, a3);
        edge_acc(evB, src, ch, b0, b1, b2, b3);
    }
    eA += nmin; eB += nmin;
    for (; eA < endA; eA++) edge_acc(__ldg(&g_edges[eA]), src, ch, a0, a1, a2, a3);
    for (; eB < endB; eB++) edge_acc(__ldg(&g_edges[eB]), src, ch, b0, b1, b2, b3);
}

__device__ __forceinline__ uint4 pack4(float2 a0, float2 a1, float2 a2, float2 a3) {
    uint4 o;
    o.x = h2u(__float22half2_rn(a0));
    o.y = h2u(__float22half2_rn(a1));
    o.z = h2u(__float22half2_rn(a2));
    o.w = h2u(__float22half2_rn(a3));
    return o;
}

// layers 1 & 2: store fp16. Epilogue restores invariants for the next call.
__global__ void __launch_bounds__(256) csr_spmm_kernel(const __half* __restrict__ src,
                                                       __half* __restrict__ dst) {
    int t = blockIdx.x * blockDim.x + threadIdx.x;
    if (t < NN) g_cnt[t] = 0;
    if (t < NTILES) g_tile_state[t] = 0ULL;
    if (t < NBUCKET) g_dhist[t] = 0;
    if (t < NTILES * NBUCKET) g_bhist[t] = 0;
    int pairIdx = t >> 3;
    if (pairIdx >= NPAIR) return;
    int ch = (t & 7) << 3;
    int rowA = __ldg(&g_perm[2 * pairIdx]);
    int rowB = __ldg(&g_perm[2 * pairIdx + 1]);
    float2 a0, a1, a2, a3, b0, b1, b2, b3;
    csr_accum_pair(rowA, rowB, ch, src, a0, a1, a2, a3, b0, b1, b2, b3);
    *reinterpret_cast<uint4*>(dst + (size_t)rowA * DD + ch) = pack4(a0, a1, a2, a3);
    *reinterpret_cast<uint4*>(dst + (size_t)rowB * DD + ch) = pack4(b0, b1, b2, b3);
}

// layer 3 fused with final: out = (ego + h1 + h2 + h3)*0.25, paired rows.
__global__ void __launch_bounds__(256) csr_spmm_final_kernel(float4* __restrict__ out) {
    int t = blockIdx.x * blockDim.x + threadIdx.x;
    int pairIdx = t >> 3;
    if (pairIdx >= NPAIR) return;
    int ch = (t & 7) << 3;
    int rowA = __ldg(&g_perm[2 * pairIdx]);
    int rowB = __ldg(&g_perm[2 * pairIdx + 1]);
    size_t baseA = (size_t)rowA * DD + ch;
    size_t baseB = (size_t)rowB * DD + ch;

    // front-batched resident loads (overlap with accumulation below)
    uint4 eA = __ldg(reinterpret_cast<const uint4*>(g_h0   + baseA));
    uint4 hA1 = __ldg(reinterpret_cast<const uint4*>(g_bufA + baseA));
    uint4 hA2 = __ldg(reinterpret_cast<const uint4*>(g_bufB + baseA));
    uint4 eB = __ldg(reinterpret_cast<const uint4*>(g_h0   + baseB));
    uint4 hB1 = __ldg(reinterpret_cast<const uint4*>(g_bufA + baseB));
    uint4 hB2 = __ldg(reinterpret_cast<const uint4*>(g_bufB + baseB));

    float2 a0, a1, a2, a3, b0, b1, b2, b3;
    csr_accum_pair(rowA, rowB, ch, g_bufB, a0, a1, a2, a3, b0, b1, b2, b3);

    #define FIN(o, eg, h1v, h2v, acc)                                          \
        {                                                                      \
            float2 _e = __half22float2(u2h(eg));                               \
            float2 _1 = __half22float2(u2h(h1v));                              \
            float2 _2 = __half22float2(u2h(h2v));                              \
            o.x = (_e.x + _1.x + _2.x + acc.x) * 0.25f;                        \
            o.y = (_e.y + _1.y + _2.y + acc.y) * 0.25f;                        \
        }
    float2 oA0, oA1, oA2, oA3, oB0, oB1, oB2, oB3;
    FIN(oA0, eA.x, hA1.x, hA2.x, a0); FIN(oA1, eA.y, hA1.y, hA2.y, a1);
    FIN(oA2, eA.z, hA1.z, hA2.z, a2); FIN(oA3, eA.w, hA1.w, hA2.w, a3);
    FIN(oB0, eB.x, hB1.x, hB2.x, b0); FIN(oB1, eB.y, hB1.y, hB2.y, b1);
    FIN(oB2, eB.z, hB1.z, hB2.z, b2); FIN(oB3, eB.w, hB1.w, hB2.w, b3);
    #undef FIN

    out[baseA / 4]     = make_float4(oA0.x, oA0.y, oA1.x, oA1.y);
    out[baseA / 4 + 1] = make_float4(oA2.x, oA2.y, oA3.x, oA3.y);
    out[baseB / 4]     = make_float4(oB0.x, oB0.y, oB1.x, oB1.y);
    out[baseB / 4 + 1] = make_float4(oB2.x, oB2.y, oB3.x, oB3.y);
}

extern "C" void kernel_launch(void* const* d_in, const int* in_sizes, int n_in,
                              void* d_out, int out_size) {
    const float* user_emb = (const float*)d_in[0];
    const float* item_emb = (const float*)d_in[1];
    const int*   adj_rows = (const int*)d_in[2];
    const int*   adj_cols = (const int*)d_in[3];
    const float* adj_vals = (const float*)d_in[4];
    float* out = (float*)d_out;

    __half *h0, *bufA, *bufB;
    cudaGetSymbolAddress((void**)&h0,   g_h0);
    cudaGetSymbolAddress((void**)&bufA, g_bufA);
    cudaGetSymbolAddress((void**)&bufB, g_bufB);

    const int T = 256;
    const int CONV_BLOCKS = (TOT8 + T - 1) / T;
    const int EDGE_BLOCKS = (EE + T - 1) / T;
    const int SPMM_BLOCKS = (NPAIR * 8 + T - 1) / T;   // must still cover NN for epilogue zeroing
    const int SPMM_BLOCKS_Z = ((NN > NPAIR * 8 ? NN : NPAIR * 8) + T - 1) / T;

    conv_hist_kernel<<<CONV_BLOCKS, T>>>((const float4*)user_emb,
                                         (const float4*)item_emb, adj_rows);
    scan_lookback_kernel<<<NTILES, T>>>();
    scatter_kernel<<<EDGE_BLOCKS, T>>>(adj_rows, adj_cols, adj_vals);

    csr_spmm_kernel<<<SPMM_BLOCKS_Z, T>>>(h0,   bufA);
    csr_spmm_kernel<<<SPMM_BLOCKS_Z, T>>>(bufA, bufB);
    csr_spmm_final_kernel<<<SPMM_BLOCKS, T>>>((float4*)out);
}

// round 15
// speedup vs baseline: 1.2446x; 1.2446x over previous
#include <cuda_runtime.h>
#include <cuda_fp16.h>
#include <cstdint>

#define NUM_USERS 100000
#define NUM_ITEMS 200000
#define NN (NUM_USERS + NUM_ITEMS)   // 300000
#define EE 2000000
#define DD 64
#define TOT (NN * DD)                // 19,200,000
#define TOT8 (TOT / 8)
#define U8  (NUM_USERS * DD / 8)

#define SCAN_TILE 4096               // 256 threads x 16 items
#define NTILES ((NN + SCAN_TILE - 1) / SCAN_TILE)   // 74 (< 148 SMs: co-resident)
#define NBUCKET 64

// ---- allocation-free scratch -----------------------------------------------
__device__ __half g_h0[TOT];       // ego in fp16
__device__ __half g_bufA[TOT];     // h1
__device__ __half g_bufB[TOT];     // h2
__device__ int    g_cnt[NN];       // histogram -> scatter cursor (zero-init; re-zeroed each call)
__device__ int    g_rowptr[NN + 1];
__device__ unsigned long long g_tile_state[NTILES];  // lookback state; 0=invalid
__device__ int    g_dhist[NBUCKET];            // degree histogram -> global bases
__device__ int    g_bhist[NTILES * NBUCKET];   // per-tile bucket histograms
__device__ int    g_perm[NN];        // rows sorted by degree (descending)
__device__ int    g_scan_done;       // ticket for last-block bucket scan
__device__ int2   g_edges[EE];       // (col, val bits) sorted by row

__device__ __forceinline__ uint32_t h2u(__half2 h) { return *reinterpret_cast<uint32_t*>(&h); }
__device__ __forceinline__ __half2  u2h(uint32_t u) { return *reinterpret_cast<__half2*>(&u); }

// ---------------------------------------------------------------------------
// conv_hist: g_h0 = fp16(concat(ue, ie))  AND  g_cnt[r]++ per edge.
// ---------------------------------------------------------------------------
__global__ void __launch_bounds__(256) conv_hist_kernel(const float4* __restrict__ ue,
                                                        const float4* __restrict__ ie,
                                                        const int* __restrict__ rows) {
    int i = blockIdx.x * blockDim.x + threadIdx.x;
    if (i < EE) atomicAdd(&g_cnt[__ldcs(&rows[i])], 1);
    if (i >= TOT8) return;
    float4 f0, f1;
    if (i < U8) {
        f0 = __ldg(&ue[2 * i]);        f1 = __ldg(&ue[2 * i + 1]);
    } else {
        f0 = __ldg(&ie[2 * (i - U8)]); f1 = __ldg(&ie[2 * (i - U8) + 1]);
    }
    uint4 h;
    h.x = h2u(__float22half2_rn(make_float2(f0.x, f0.y)));
    h.y = h2u(__float22half2_rn(make_float2(f0.z, f0.w)));
    h.z = h2u(__float22half2_rn(make_float2(f1.x, f1.y)));
    h.w = h2u(__float22half2_rn(make_float2(f1.z, f1.w)));
    reinterpret_cast<uint4*>(g_h0)[i] = h;
}

// ---------------------------------------------------------------------------
// Single-pass decoupled-lookback scan + degree histogram + (last block)
// descending bucket-base scan.
// ---------------------------------------------------------------------------
__global__ void __launch_bounds__(256) scan_lookback_kernel() {
    __shared__ int s_warp[8];
    __shared__ int s_total;
    __shared__ uint32_t s_prefix;
    __shared__ int s_hist[NBUCKET];
    __shared__ int s_ticket;
    int tid = threadIdx.x;
    int blk = blockIdx.x;
    int base = blk * SCAN_TILE + tid * 16;
    if (tid < NBUCKET) s_hist[tid] = 0;

    int v[16];
    #pragma unroll
    for (int j = 0; j < 4; j++) {
        int idx = base + j * 4;
        if (idx + 3 < NN) {
            int4 t4 = *reinterpret_cast<const int4*>(&g_cnt[idx]);
            v[j*4] = t4.x; v[j*4+1] = t4.y; v[j*4+2] = t4.z; v[j*4+3] = t4.w;
        } else {
            v[j*4]   = (idx     < NN) ? g_cnt[idx]     : 0;
            v[j*4+1] = (idx + 1 < NN) ? g_cnt[idx + 1] : 0;
            v[j*4+2] = (idx + 2 < NN) ? g_cnt[idx + 2] : 0;
            v[j*4+3] = (idx + 3 < NN) ? g_cnt[idx + 3] : 0;
        }
    }
    int tsum = 0;
    #pragma unroll
    for (int j = 0; j < 16; j++) tsum += v[j];

    int lane = tid & 31, wid = tid >> 5;
    int x = tsum;
    #pragma unroll
    for (int d = 1; d < 32; d <<= 1) {
        int y = __shfl_up_sync(0xffffffffu, x, d);
        if (lane >= d) x += y;
    }
    if (lane == 31) s_warp[wid] = x;
    __syncthreads();

    #pragma unroll
    for (int j = 0; j < 16; j++) {
        if (base + j < NN) atomicAdd(&s_hist[v[j] < NBUCKET - 1 ? v[j] : NBUCKET - 1], 1);
    }

    if (wid == 0) {
        int w = (lane < 8) ? s_warp[lane] : 0;
        #pragma unroll
        for (int d = 1; d < 8; d <<= 1) {
            int y = __shfl_up_sync(0xffffffffu, w, d);
            if (lane >= d) w += y;
        }
        if (lane < 8) s_warp[lane] = w;
    }
    __syncthreads();
    int woff = (wid > 0) ? s_warp[wid - 1] : 0;
    int texcl = woff + x - tsum;
    if (tid == 255) s_total = woff + x;
    if (tid < NBUCKET) {
        int h = s_hist[tid];
        g_bhist[blk * NBUCKET + tid] = h;
        if (h) atomicAdd(&g_dhist[tid], h);
    }
    __syncthreads();

    if (tid < 32) {
        if (blk == 0) {
            if (lane == 0) {
                s_prefix = 0;
                *(volatile unsigned long long*)&g_tile_state[0] =
                    (2ULL << 32) | (uint32_t)s_total;
            }
        } else {
            if (lane == 0)
                *(volatile unsigned long long*)&g_tile_state[blk] =
                    (1ULL << 32) | (uint32_t)s_total;
            unsigned long long prefix = 0;
            int b2 = blk - 1;
            while (true) {
                int p = b2 - lane;
                unsigned long long s;
                if (p < 0) {
                    s = (2ULL << 32);
                } else {
                    do { s = *(volatile unsigned long long*)&g_tile_state[p]; } while (s == 0ULL);
                }
                uint32_t st  = (uint32_t)(s >> 32);
                uint32_t val = (uint32_t)s;
                unsigned m = __ballot_sync(0xffffffffu, st == 2u);
                if (m) {
                    int k = __ffs(m) - 1;
                    prefix += __reduce_add_sync(0xffffffffu, (lane <= k) ? val : 0u);
                    break;
                }
                prefix += __reduce_add_sync(0xffffffffu, val);
                b2 -= 32;
            }
            if (lane == 0) {
                s_prefix = (uint32_t)prefix;
                *(volatile unsigned long long*)&g_tile_state[blk] =
                    (2ULL << 32) | (uint32_t)(prefix + (uint32_t)s_total);
            }
        }
    }
    __syncthreads();

    int g = (int)s_prefix + texcl;
    #pragma unroll
    for (int j = 0; j < 16; j++) {
        int idx = base + j;
        if (idx < NN) {
            g_cnt[idx] = g;
            g_rowptr[idx + 1] = g + v[j];
            g += v[j];
        }
    }
    if (blk == 0 && tid == 0) g_rowptr[0] = 0;

    __threadfence();
    __syncthreads();
    if (tid == 0) s_ticket = atomicAdd(&g_scan_done, 1);
    __syncthreads();
    if (s_ticket == NTILES - 1 && tid < 32) {
        __threadfence();
        int l = tid;
        int a = g_dhist[63 - l];
        int b = g_dhist[31 - l];
        int xa = a, xb = b;
        #pragma unroll
        for (int d = 1; d < 32; d <<= 1) {
            int ya = __shfl_up_sync(0xffffffffu, xa, d);
            int yb = __shfl_up_sync(0xffffffffu, xb, d);
            if (l >= d) { xa += ya; xb += yb; }
        }
        int totalA = __shfl_sync(0xffffffffu, xa, 31);
        g_dhist[63 - l] = xa - a;
        g_dhist[31 - l] = totalA + xb - b;
        if (l == 0) g_scan_done = 0;
    }
}

// ---------------------------------------------------------------------------
// scatter: edges into row buckets; blocks 0..NTILES-1 also build the
// degree-sorted perm for their row tile.
// ---------------------------------------------------------------------------
__global__ void __launch_bounds__(256) scatter_kernel(const int* __restrict__ rows,
                                                      const int* __restrict__ cols,
                                                      const float* __restrict__ vals) {
    __shared__ int s_off[NBUCKET];
    int tid = threadIdx.x;
    int blk = blockIdx.x;

    if (blk < NTILES) {
        int b = tid >> 2, q = tid & 3;
        int per = (blk + 3) >> 2;
        int p0 = q * per;
        int p1 = (blk < p0 + per) ? blk : p0 + per;
        int sum = 0;
        for (int p = p0; p < p1; p++) sum += __ldg(&g_bhist[p * NBUCKET + b]);
        sum += __shfl_xor_sync(0xffffffffu, sum, 1);
        sum += __shfl_xor_sync(0xffffffffu, sum, 2);
        if (q == 0) s_off[b] = __ldg(&g_dhist[b]) + sum;
        __syncthreads();
        int base = blk * SCAN_TILE + tid * 16;
        #pragma unroll
        for (int j = 0; j < 16; j++) {
            int idx = base + j;
            if (idx < NN) {
                int deg = __ldg(&g_rowptr[idx + 1]) - __ldg(&g_rowptr[idx]);
                int bb = deg < NBUCKET - 1 ? deg : NBUCKET - 1;
                int pos = atomicAdd(&s_off[bb], 1);
                g_perm[pos] = idx;
            }
        }
    }

    int e = blk * blockDim.x + tid;
    if (e >= EE) return;
    int r = __ldcs(&rows[e]);
    int c = __ldcs(&cols[e]);
    float v = __ldcs(&vals[e]);
    int pos = atomicAdd(&g_cnt[r], 1);
    g_edges[pos] = make_int2(c, __float_as_int(v));
}

// ---------------------------------------------------------------------------
// CSR row accumulation: 16 threads/row, each owns an 8B (4-half) chunk.
// Thin threads, max TLP; fp32 accumulation; simple loop (ptxas batches).
// ---------------------------------------------------------------------------
__device__ __forceinline__ void csr_accum16(int row, int ch,
                                            const __half* __restrict__ src,
                                            float2& a0, float2& a1) {
    int e   = __ldg(&g_rowptr[row]);
    int end = __ldg(&g_rowptr[row + 1]);
    a0 = make_float2(0.f, 0.f); a1 = a0;
    #pragma unroll 2
    for (; e < end; e++) {
        int2 ev = __ldg(&g_edges[e]);
        float v = __int_as_float(ev.y);
        uint2 x = __ldg(reinterpret_cast<const uint2*>(src + (size_t)ev.x * DD + ch));
        float2 f0 = __half22float2(u2h(x.x));
        float2 f1 = __half22float2(u2h(x.y));
        a0.x += v * f0.x; a0.y += v * f0.y;
        a1.x += v * f1.x; a1.y += v * f1.y;
    }
}

// layers 1 & 2: store fp16. Epilogue restores invariants for the next call.
__global__ void __launch_bounds__(256) csr_spmm_kernel(const __half* __restrict__ src,
                                                       __half* __restrict__ dst) {
    int t = blockIdx.x * blockDim.x + threadIdx.x;
    if (t < NN) g_cnt[t] = 0;
    if (t < NTILES) g_tile_state[t] = 0ULL;
    if (t < NBUCKET) g_dhist[t] = 0;
    if (t < NTILES * NBUCKET) g_bhist[t] = 0;
    int rowIdx = t >> 4;
    if (rowIdx >= NN) return;
    int row = __ldg(&g_perm[rowIdx]);     // degree-sorted (heavy first)
    int ch = (t & 15) << 2;               // half offset 0,4,...,60 (8B chunks)
    float2 a0, a1;
    csr_accum16(row, ch, src, a0, a1);
    uint2 o;
    o.x = h2u(__float22half2_rn(a0));
    o.y = h2u(__float22half2_rn(a1));
    *reinterpret_cast<uint2*>(dst + (size_t)row * DD + ch) = o;
}

// layer 3 fused with final: out = (ego + h1 + h2 + h3)*0.25.
// Resident row loads front-batched before the accumulation loop.
__global__ void __launch_bounds__(256) csr_spmm_final_kernel(float4* __restrict__ out) {
    int t = blockIdx.x * blockDim.x + threadIdx.x;
    int rowIdx = t >> 4;
    if (rowIdx >= NN) return;
    int row = __ldg(&g_perm[rowIdx]);
    int ch = (t & 15) << 2;
    size_t base = (size_t)row * DD + ch;

    uint2 ue0 = __ldg(reinterpret_cast<const uint2*>(g_h0   + base));
    uint2 uh1 = __ldg(reinterpret_cast<const uint2*>(g_bufA + base));
    uint2 uh2 = __ldg(reinterpret_cast<const uint2*>(g_bufB + base));

    float2 a0, a1;
    csr_accum16(row, ch, g_bufB, a0, a1);   // h3 accum from h2

    float2 e0 = __half22float2(u2h(ue0.x)), e1 = __half22float2(u2h(ue0.y));
    float2 h10 = __half22float2(u2h(uh1.x)), h11 = __half22float2(u2h(uh1.y));
    float2 h20 = __half22float2(u2h(uh2.x)), h21 = __half22float2(u2h(uh2.y));

    float4 o;
    o.x = (e0.x + h10.x + h20.x + a0.x) * 0.25f;
    o.y = (e0.y + h10.y + h20.y + a0.y) * 0.25f;
    o.z = (e1.x + h11.x + h21.x + a1.x) * 0.25f;
    o.w = (e1.y + h11.y + h21.y + a1.y) * 0.25f;
    out[base / 4] = o;
}

extern "C" void kernel_launch(void* const* d_in, const int* in_sizes, int n_in,
                              void* d_out, int out_size) {
    const float* user_emb = (const float*)d_in[0];
    const float* item_emb = (const float*)d_in[1];
    const int*   adj_rows = (const int*)d_in[2];
    const int*   adj_cols = (const int*)d_in[3];
    const float* adj_vals = (const float*)d_in[4];
    float* out = (float*)d_out;

    __half *h0, *bufA, *bufB;
    cudaGetSymbolAddress((void**)&h0,   g_h0);
    cudaGetSymbolAddress((void**)&bufA, g_bufA);
    cudaGetSymbolAddress((void**)&bufB, g_bufB);

    const int T = 256;
    const int CONV_BLOCKS = (TOT8 + T - 1) / T;
    const int EDGE_BLOCKS = (EE + T - 1) / T;
    const int SPMM_BLOCKS = ((size_t)NN * 16 + T - 1) / T;

    conv_hist_kernel<<<CONV_BLOCKS, T>>>((const float4*)user_emb,
                                         (const float4*)item_emb, adj_rows);
    scan_lookback_kernel<<<NTILES, T>>>();
    scatter_kernel<<<EDGE_BLOCKS, T>>>(adj_rows, adj_cols, adj_vals);

    csr_spmm_kernel<<<SPMM_BLOCKS, T>>>(h0,   bufA);
    csr_spmm_kernel<<<SPMM_BLOCKS, T>>>(bufA, bufB);
    csr_spmm_final_kernel<<<SPMM_BLOCKS, T>>>((float4*)out);
}

// round 16
// speedup vs baseline: 1.5552x; 1.2496x over previous
#include <cuda_runtime.h>
#include <cuda_fp16.h>
#include <cstdint>

#define NUM_USERS 100000
#define NUM_ITEMS 200000
#define NN (NUM_USERS + NUM_ITEMS)   // 300000
#define EE 2000000
#define DD 64
#define TOT (NN * DD)                // 19,200,000
#define TOT8 (TOT / 8)
#define U8  (NUM_USERS * DD / 8)

#define SCAN_TILE 4096               // 256 threads x 16 items
#define NTILES ((NN + SCAN_TILE - 1) / SCAN_TILE)   // 74 (< 148 SMs: co-resident)
#define NBUCKET 64

// ---- allocation-free scratch -----------------------------------------------
__device__ __half g_h0[TOT];       // ego in fp16
__device__ __half g_bufA[TOT];     // h1
__device__ __half g_bufB[TOT];     // h2
__device__ int    g_cnt[NN];       // histogram -> scatter cursor (zero-init; re-zeroed each call)
__device__ int    g_rowptr[NN + 1];
__device__ unsigned long long g_tile_state[NTILES];  // lookback state; 0=invalid
__device__ int    g_dhist[NBUCKET];            // degree histogram -> global bases
__device__ int    g_bhist[NTILES * NBUCKET];   // per-tile bucket histograms
__device__ int    g_perm[NN];        // rows sorted by degree (descending)
__device__ int    g_scan_done;       // ticket for last-block bucket scan
__device__ int2   g_edges[EE];       // (col, val bits) sorted by row

__device__ __forceinline__ uint32_t h2u(__half2 h) { return *reinterpret_cast<uint32_t*>(&h); }
__device__ __forceinline__ __half2  u2h(uint32_t u) { return *reinterpret_cast<__half2*>(&u); }

// ---------------------------------------------------------------------------
// conv_hist: g_h0 = fp16(concat(ue, ie))  AND  g_cnt[r]++ per edge.
// ---------------------------------------------------------------------------
__global__ void __launch_bounds__(256) conv_hist_kernel(const float4* __restrict__ ue,
                                                        const float4* __restrict__ ie,
                                                        const int* __restrict__ rows) {
    int i = blockIdx.x * blockDim.x + threadIdx.x;
    if (i < EE) atomicAdd(&g_cnt[__ldcs(&rows[i])], 1);
    if (i >= TOT8) return;
    float4 f0, f1;
    if (i < U8) {
        f0 = __ldg(&ue[2 * i]);        f1 = __ldg(&ue[2 * i + 1]);
    } else {
        f0 = __ldg(&ie[2 * (i - U8)]); f1 = __ldg(&ie[2 * (i - U8) + 1]);
    }
    uint4 h;
    h.x = h2u(__float22half2_rn(make_float2(f0.x, f0.y)));
    h.y = h2u(__float22half2_rn(make_float2(f0.z, f0.w)));
    h.z = h2u(__float22half2_rn(make_float2(f1.x, f1.y)));
    h.w = h2u(__float22half2_rn(make_float2(f1.z, f1.w)));
    reinterpret_cast<uint4*>(g_h0)[i] = h;
}

// ---------------------------------------------------------------------------
// Single-pass decoupled-lookback scan + degree histogram + (last block)
// descending bucket-base scan.
// ---------------------------------------------------------------------------
__global__ void __launch_bounds__(256) scan_lookback_kernel() {
    __shared__ int s_warp[8];
    __shared__ int s_total;
    __shared__ uint32_t s_prefix;
    __shared__ int s_hist[NBUCKET];
    __shared__ int s_ticket;
    int tid = threadIdx.x;
    int blk = blockIdx.x;
    int base = blk * SCAN_TILE + tid * 16;
    if (tid < NBUCKET) s_hist[tid] = 0;

    int v[16];
    #pragma unroll
    for (int j = 0; j < 4; j++) {
        int idx = base + j * 4;
        if (idx + 3 < NN) {
            int4 t4 = *reinterpret_cast<const int4*>(&g_cnt[idx]);
            v[j*4] = t4.x; v[j*4+1] = t4.y; v[j*4+2] = t4.z; v[j*4+3] = t4.w;
        } else {
            v[j*4]   = (idx     < NN) ? g_cnt[idx]     : 0;
            v[j*4+1] = (idx + 1 < NN) ? g_cnt[idx + 1] : 0;
            v[j*4+2] = (idx + 2 < NN) ? g_cnt[idx + 2] : 0;
            v[j*4+3] = (idx + 3 < NN) ? g_cnt[idx + 3] : 0;
        }
    }
    int tsum = 0;
    #pragma unroll
    for (int j = 0; j < 16; j++) tsum += v[j];

    int lane = tid & 31, wid = tid >> 5;
    int x = tsum;
    #pragma unroll
    for (int d = 1; d < 32; d <<= 1) {
        int y = __shfl_up_sync(0xffffffffu, x, d);
        if (lane >= d) x += y;
    }
    if (lane == 31) s_warp[wid] = x;
    __syncthreads();

    #pragma unroll
    for (int j = 0; j < 16; j++) {
        if (base + j < NN) atomicAdd(&s_hist[v[j] < NBUCKET - 1 ? v[j] : NBUCKET - 1], 1);
    }

    if (wid == 0) {
        int w = (lane < 8) ? s_warp[lane] : 0;
        #pragma unroll
        for (int d = 1; d < 8; d <<= 1) {
            int y = __shfl_up_sync(0xffffffffu, w, d);
            if (lane >= d) w += y;
        }
        if (lane < 8) s_warp[lane] = w;
    }
    __syncthreads();
    int woff = (wid > 0) ? s_warp[wid - 1] : 0;
    int texcl = woff + x - tsum;
    if (tid == 255) s_total = woff + x;
    if (tid < NBUCKET) {
        int h = s_hist[tid];
        g_bhist[blk * NBUCKET + tid] = h;
        if (h) atomicAdd(&g_dhist[tid], h);
    }
    __syncthreads();

    // warp 0: decoupled lookback
    if (tid < 32) {
        if (blk == 0) {
            if (lane == 0) {
                s_prefix = 0;
                *(volatile unsigned long long*)&g_tile_state[0] =
                    (2ULL << 32) | (uint32_t)s_total;
            }
        } else {
            if (lane == 0)
                *(volatile unsigned long long*)&g_tile_state[blk] =
                    (1ULL << 32) | (uint32_t)s_total;
            unsigned long long prefix = 0;
            int b2 = blk - 1;
            while (true) {
                int p = b2 - lane;
                unsigned long long s;
                if (p < 0) {
                    s = (2ULL << 32);
                } else {
                    do { s = *(volatile unsigned long long*)&g_tile_state[p]; } while (s == 0ULL);
                }
                uint32_t st  = (uint32_t)(s >> 32);
                uint32_t val = (uint32_t)s;
                unsigned m = __ballot_sync(0xffffffffu, st == 2u);
                if (m) {
                    int k = __ffs(m) - 1;
                    prefix += __reduce_add_sync(0xffffffffu, (lane <= k) ? val : 0u);
                    break;
                }
                prefix += __reduce_add_sync(0xffffffffu, val);
                b2 -= 32;
            }
            if (lane == 0) {
                s_prefix = (uint32_t)prefix;
                *(volatile unsigned long long*)&g_tile_state[blk] =
                    (2ULL << 32) | (uint32_t)(prefix + (uint32_t)s_total);
            }
        }
    }
    __syncthreads();

    int g = (int)s_prefix + texcl;
    #pragma unroll
    for (int j = 0; j < 16; j++) {
        int idx = base + j;
        if (idx < NN) {
            g_cnt[idx] = g;
            g_rowptr[idx + 1] = g + v[j];
            g += v[j];
        }
    }
    if (blk == 0 && tid == 0) g_rowptr[0] = 0;

    // last block: descending bucket-base scan over g_dhist
    __threadfence();
    __syncthreads();
    if (tid == 0) s_ticket = atomicAdd(&g_scan_done, 1);
    __syncthreads();
    if (s_ticket == NTILES - 1 && tid < 32) {
        __threadfence();
        int l = tid;
        int a = g_dhist[63 - l];
        int b = g_dhist[31 - l];
        int xa = a, xb = b;
        #pragma unroll
        for (int d = 1; d < 32; d <<= 1) {
            int ya = __shfl_up_sync(0xffffffffu, xa, d);
            int yb = __shfl_up_sync(0xffffffffu, xb, d);
            if (l >= d) { xa += ya; xb += yb; }
        }
        int totalA = __shfl_sync(0xffffffffu, xa, 31);
        g_dhist[63 - l] = xa - a;
        g_dhist[31 - l] = totalA + xb - b;
        if (l == 0) g_scan_done = 0;
    }
}

// ---------------------------------------------------------------------------
// scatter: edges into row buckets; blocks 0..NTILES-1 also build the
// degree-sorted perm for their row tile.
// ---------------------------------------------------------------------------
__global__ void __launch_bounds__(256) scatter_kernel(const int* __restrict__ rows,
                                                      const int* __restrict__ cols,
                                                      const float* __restrict__ vals) {
    __shared__ int s_off[NBUCKET];
    int tid = threadIdx.x;
    int blk = blockIdx.x;

    if (blk < NTILES) {
        int b = tid >> 2, q = tid & 3;
        int per = (blk + 3) >> 2;
        int p0 = q * per;
        int p1 = (blk < p0 + per) ? blk : p0 + per;
        int sum = 0;
        for (int p = p0; p < p1; p++) sum += __ldg(&g_bhist[p * NBUCKET + b]);
        sum += __shfl_xor_sync(0xffffffffu, sum, 1);
        sum += __shfl_xor_sync(0xffffffffu, sum, 2);
        if (q == 0) s_off[b] = __ldg(&g_dhist[b]) + sum;
        __syncthreads();
        int base = blk * SCAN_TILE + tid * 16;
        #pragma unroll
        for (int j = 0; j < 16; j++) {
            int idx = base + j;
            if (idx < NN) {
                int deg = __ldg(&g_rowptr[idx + 1]) - __ldg(&g_rowptr[idx]);
                int bb = deg < NBUCKET - 1 ? deg : NBUCKET - 1;
                int pos = atomicAdd(&s_off[bb], 1);
                g_perm[pos] = idx;
            }
        }
    }

    int e = blk * blockDim.x + tid;
    if (e >= EE) return;
    int r = __ldcs(&rows[e]);
    int c = __ldcs(&cols[e]);
    float v = __ldcs(&vals[e]);
    int pos = atomicAdd(&g_cnt[r], 1);
    g_edges[pos] = make_int2(c, __float_as_int(v));
}

// ---------------------------------------------------------------------------
// CSR row accumulation core: simple loop, unroll 2. 8 threads/row, fp32 accum.
// ---------------------------------------------------------------------------
__device__ __forceinline__ void csr_accum(int row, int ch,
                                          const __half* __restrict__ src,
                                          float2& a0, float2& a1,
                                          float2& a2, float2& a3) {
    int e   = __ldg(&g_rowptr[row]);
    int end = __ldg(&g_rowptr[row + 1]);
    a0 = make_float2(0.f, 0.f); a1 = a0; a2 = a0; a3 = a0;
    #pragma unroll 2
    for (; e < end; e++) {
        int2 ev = __ldg(&g_edges[e]);
        float v = __int_as_float(ev.y);
        uint4 x = __ldg(reinterpret_cast<const uint4*>(src + (size_t)ev.x * DD + ch));
        float2 f0 = __half22float2(u2h(x.x));
        float2 f1 = __half22float2(u2h(x.y));
        float2 f2 = __half22float2(u2h(x.z));
        float2 f3 = __half22float2(u2h(x.w));
        a0.x += v * f0.x; a0.y += v * f0.y;
        a1.x += v * f1.x; a1.y += v * f1.y;
        a2.x += v * f2.x; a2.y += v * f2.y;
        a3.x += v * f3.x; a3.y += v * f3.y;
    }
}

// layers 1 & 2: store fp16. Epilogue restores invariants for the next call.
__global__ void __launch_bounds__(256) csr_spmm_kernel(const __half* __restrict__ src,
                                                       __half* __restrict__ dst) {
    int t = blockIdx.x * blockDim.x + threadIdx.x;
    if (t < NN) g_cnt[t] = 0;
    if (t < NTILES) g_tile_state[t] = 0ULL;
    if (t < NBUCKET) g_dhist[t] = 0;
    if (t < NTILES * NBUCKET) g_bhist[t] = 0;
    int rowIdx = t >> 3;
    if (rowIdx >= NN) return;
    int row = __ldg(&g_perm[rowIdx]);     // degree-sorted (heavy first)
    int ch = (t & 7) << 3;
    float2 a0, a1, a2, a3;
    csr_accum(row, ch, src, a0, a1, a2, a3);
    uint4 o;
    o.x = h2u(__float22half2_rn(a0));
    o.y = h2u(__float22half2_rn(a1));
    o.z = h2u(__float22half2_rn(a2));
    o.w = h2u(__float22half2_rn(a3));
    *reinterpret_cast<uint4*>(dst + (size_t)row * DD + ch) = o;
}

// layer 3 fused with final: out = (ego + h1 + h2 + h3)*0.25.
// ego/h1/h2 read from fp16 L2-resident buffers.
__global__ void __launch_bounds__(256) csr_spmm_final_kernel(float4* __restrict__ out) {
    int t = blockIdx.x * blockDim.x + threadIdx.x;
    int rowIdx = t >> 3;
    if (rowIdx >= NN) return;
    int row = __ldg(&g_perm[rowIdx]);
    int ch = (t & 7) << 3;
    float2 a0, a1, a2, a3;
    csr_accum(row, ch, g_bufB, a0, a1, a2, a3);   // h3 accum from h2

    size_t base = (size_t)row * DD + ch;
    uint4 ue0 = __ldg(reinterpret_cast<const uint4*>(g_h0   + base));
    uint4 uh1 = __ldg(reinterpret_cast<const uint4*>(g_bufA + base));
    uint4 uh2 = __ldg(reinterpret_cast<const uint4*>(g_bufB + base));
    float2 e00 = __half22float2(u2h(ue0.x)), e01 = __half22float2(u2h(ue0.y));
    float2 e02 = __half22float2(u2h(ue0.z)), e03 = __half22float2(u2h(ue0.w));
    float2 h10 = __half22float2(u2h(uh1.x)), h11 = __half22float2(u2h(uh1.y));
    float2 h12 = __half22float2(u2h(uh1.z)), h13 = __half22float2(u2h(uh1.w));
    float2 h20 = __half22float2(u2h(uh2.x)), h21 = __half22float2(u2h(uh2.y));
    float2 h22 = __half22float2(u2h(uh2.z)), h23 = __half22float2(u2h(uh2.w));

    float4 o0, o1;
    o0.x = (e00.x + h10.x + h20.x + a0.x) * 0.25f;
    o0.y = (e00.y + h10.y + h20.y + a0.y) * 0.25f;
    o0.z = (e01.x + h11.x + h21.x + a1.x) * 0.25f;
    o0.w = (e01.y + h11.y + h21.y + a1.y) * 0.25f;
    o1.x = (e02.x + h12.x + h22.x + a2.x) * 0.25f;
    o1.y = (e02.y + h12.y + h22.y + a2.y) * 0.25f;
    o1.z = (e03.x + h13.x + h23.x + a3.x) * 0.25f;
    o1.w = (e03.y + h13.y + h23.y + a3.y) * 0.25f;
    out[base / 4]     = o0;
    out[base / 4 + 1] = o1;
}

extern "C" void kernel_launch(void* const* d_in, const int* in_sizes, int n_in,
                              void* d_out, int out_size) {
    const float* user_emb = (const float*)d_in[0];
    const float* item_emb = (const float*)d_in[1];
    const int*   adj_rows = (const int*)d_in[2];
    const int*   adj_cols = (const int*)d_in[3];
    const float* adj_vals = (const float*)d_in[4];
    float* out = (float*)d_out;

    __half *h0, *bufA, *bufB;
    cudaGetSymbolAddress((void**)&h0,   g_h0);
    cudaGetSymbolAddress((void**)&bufA, g_bufA);
    cudaGetSymbolAddress((void**)&bufB, g_bufB);

    const int T = 256;
    const int CONV_BLOCKS = (TOT8 + T - 1) / T;
    const int EDGE_BLOCKS = (EE + T - 1) / T;
    const int SPMM_BLOCKS = (NN * 8 + T - 1) / T;

    conv_hist_kernel<<<CONV_BLOCKS, T>>>((const float4*)user_emb,
                                         (const float4*)item_emb, adj_rows);
    scan_lookback_kernel<<<NTILES, T>>>();
    scatter_kernel<<<EDGE_BLOCKS, T>>>(adj_rows, adj_cols, adj_vals);

    csr_spmm_kernel<<<SPMM_BLOCKS, T>>>(h0,   bufA);
    csr_spmm_kernel<<<SPMM_BLOCKS, T>>>(bufA, bufB);
    csr_spmm_final_kernel<<<SPMM_BLOCKS, T>>>((float4*)out);
}

// round 17
// speedup vs baseline: 1.5618x; 1.0042x over previous
#include <cuda_runtime.h>
#include <cuda_fp16.h>
#include <cstdint>

#define NUM_USERS 100000
#define NUM_ITEMS 200000
#define NN (NUM_USERS + NUM_ITEMS)   // 300000
#define EE 2000000
#define DD 64
#define TOT (NN * DD)                // 19,200,000
#define TOT8 (TOT / 8)
#define U8  (NUM_USERS * DD / 8)

#define SCAN_TILE 4096               // 256 threads x 16 items
#define NTILES ((NN + SCAN_TILE - 1) / SCAN_TILE)   // 74 (< 148 SMs: co-resident)
#define NBUCKET 64

// ---- allocation-free scratch -----------------------------------------------
__device__ __half g_h0[TOT];       // ego in fp16
__device__ __half g_bufA[TOT];     // h1
__device__ __half g_bufB[TOT];     // h2
__device__ int    g_cnt[NN];       // histogram -> scatter cursor (zero-init; re-zeroed each call)
__device__ int    g_rowptr[NN + 1];
__device__ unsigned long long g_tile_state[NTILES];  // lookback state; 0=invalid
__device__ int    g_dhist[NBUCKET];            // degree histogram -> global bases
__device__ int    g_bhist[NTILES * NBUCKET];   // per-tile bucket histograms
__device__ int    g_perm[NN];        // rows sorted by degree (descending)
__device__ int    g_scan_done;       // ticket for last-block bucket scan
__device__ int2   g_edges[EE];       // (col, val bits) sorted by row

__device__ __forceinline__ uint32_t h2u(__half2 h) { return *reinterpret_cast<uint32_t*>(&h); }
__device__ __forceinline__ __half2  u2h(uint32_t u) { return *reinterpret_cast<__half2*>(&u); }

// ---------------------------------------------------------------------------
// hist: g_cnt[r]++ per edge (precondition: g_cnt == 0 from zero-init/epilogue)
// ---------------------------------------------------------------------------
__global__ void __launch_bounds__(256) hist_kernel(const int* __restrict__ rows) {
    int e = blockIdx.x * blockDim.x + threadIdx.x;
    if (e >= EE) return;
    atomicAdd(&g_cnt[__ldcs(&rows[e])], 1);
}

// ---------------------------------------------------------------------------
// Single-pass decoupled-lookback scan + degree histogram + (last block)
// descending bucket-base scan.
// ---------------------------------------------------------------------------
__global__ void __launch_bounds__(256) scan_lookback_kernel() {
    __shared__ int s_warp[8];
    __shared__ int s_total;
    __shared__ uint32_t s_prefix;
    __shared__ int s_hist[NBUCKET];
    __shared__ int s_ticket;
    int tid = threadIdx.x;
    int blk = blockIdx.x;
    int base = blk * SCAN_TILE + tid * 16;
    if (tid < NBUCKET) s_hist[tid] = 0;

    int v[16];
    #pragma unroll
    for (int j = 0; j < 4; j++) {
        int idx = base + j * 4;
        if (idx + 3 < NN) {
            int4 t4 = *reinterpret_cast<const int4*>(&g_cnt[idx]);
            v[j*4] = t4.x; v[j*4+1] = t4.y; v[j*4+2] = t4.z; v[j*4+3] = t4.w;
        } else {
            v[j*4]   = (idx     < NN) ? g_cnt[idx]     : 0;
            v[j*4+1] = (idx + 1 < NN) ? g_cnt[idx + 1] : 0;
            v[j*4+2] = (idx + 2 < NN) ? g_cnt[idx + 2] : 0;
            v[j*4+3] = (idx + 3 < NN) ? g_cnt[idx + 3] : 0;
        }
    }
    int tsum = 0;
    #pragma unroll
    for (int j = 0; j < 16; j++) tsum += v[j];

    int lane = tid & 31, wid = tid >> 5;
    int x = tsum;
    #pragma unroll
    for (int d = 1; d < 32; d <<= 1) {
        int y = __shfl_up_sync(0xffffffffu, x, d);
        if (lane >= d) x += y;
    }
    if (lane == 31) s_warp[wid] = x;
    __syncthreads();

    #pragma unroll
    for (int j = 0; j < 16; j++) {
        if (base + j < NN) atomicAdd(&s_hist[v[j] < NBUCKET - 1 ? v[j] : NBUCKET - 1], 1);
    }

    if (wid == 0) {
        int w = (lane < 8) ? s_warp[lane] : 0;
        #pragma unroll
        for (int d = 1; d < 8; d <<= 1) {
            int y = __shfl_up_sync(0xffffffffu, w, d);
            if (lane >= d) w += y;
        }
        if (lane < 8) s_warp[lane] = w;
    }
    __syncthreads();
    int woff = (wid > 0) ? s_warp[wid - 1] : 0;
    int texcl = woff + x - tsum;
    if (tid == 255) s_total = woff + x;
    if (tid < NBUCKET) {
        int h = s_hist[tid];
        g_bhist[blk * NBUCKET + tid] = h;
        if (h) atomicAdd(&g_dhist[tid], h);
    }
    __syncthreads();

    // warp 0: decoupled lookback
    if (tid < 32) {
        if (blk == 0) {
            if (lane == 0) {
                s_prefix = 0;
                *(volatile unsigned long long*)&g_tile_state[0] =
                    (2ULL << 32) | (uint32_t)s_total;
            }
        } else {
            if (lane == 0)
                *(volatile unsigned long long*)&g_tile_state[blk] =
                    (1ULL << 32) | (uint32_t)s_total;
            unsigned long long prefix = 0;
            int b2 = blk - 1;
            while (true) {
                int p = b2 - lane;
                unsigned long long s;
                if (p < 0) {
                    s = (2ULL << 32);
                } else {
                    do { s = *(volatile unsigned long long*)&g_tile_state[p]; } while (s == 0ULL);
                }
                uint32_t st  = (uint32_t)(s >> 32);
                uint32_t val = (uint32_t)s;
                unsigned m = __ballot_sync(0xffffffffu, st == 2u);
                if (m) {
                    int k = __ffs(m) - 1;
                    prefix += __reduce_add_sync(0xffffffffu, (lane <= k) ? val : 0u);
                    break;
                }
                prefix += __reduce_add_sync(0xffffffffu, val);
                b2 -= 32;
            }
            if (lane == 0) {
                s_prefix = (uint32_t)prefix;
                *(volatile unsigned long long*)&g_tile_state[blk] =
                    (2ULL << 32) | (uint32_t)(prefix + (uint32_t)s_total);
            }
        }
    }
    __syncthreads();

    int g = (int)s_prefix + texcl;
    #pragma unroll
    for (int j = 0; j < 16; j++) {
        int idx = base + j;
        if (idx < NN) {
            g_cnt[idx] = g;
            g_rowptr[idx + 1] = g + v[j];
            g += v[j];
        }
    }
    if (blk == 0 && tid == 0) g_rowptr[0] = 0;

    // last block: descending bucket-base scan over g_dhist
    __threadfence();
    __syncthreads();
    if (tid == 0) s_ticket = atomicAdd(&g_scan_done, 1);
    __syncthreads();
    if (s_ticket == NTILES - 1 && tid < 32) {
        __threadfence();
        int l = tid;
        int a = g_dhist[63 - l];
        int b = g_dhist[31 - l];
        int xa = a, xb = b;
        #pragma unroll
        for (int d = 1; d < 32; d <<= 1) {
            int ya = __shfl_up_sync(0xffffffffu, xa, d);
            int yb = __shfl_up_sync(0xffffffffu, xb, d);
            if (l >= d) { xa += ya; xb += yb; }
        }
        int totalA = __shfl_sync(0xffffffffu, xa, 31);
        g_dhist[63 - l] = xa - a;
        g_dhist[31 - l] = totalA + xb - b;
        if (l == 0) g_scan_done = 0;
    }
}

// ---------------------------------------------------------------------------
// conv_scatter: three co-scheduled streams that bind on different resources:
//   (1) conv: ego -> fp16 g_h0 (DRAM-read bound)
//   (2) perm build for row tiles (blocks < NTILES, shared-mem atomics)
//   (3) edge scatter into row buckets (L2-atomic bound)
// ---------------------------------------------------------------------------
__global__ void __launch_bounds__(256) conv_scatter_kernel(
    const float4* __restrict__ ue, const float4* __restrict__ ie,
    const int* __restrict__ rows, const int* __restrict__ cols,
    const float* __restrict__ vals) {
    __shared__ int s_off[NBUCKET];
    int tid = threadIdx.x;
    int blk = blockIdx.x;
    int i = blk * blockDim.x + tid;

    // (1) conv — issue DRAM loads early
    if (i < TOT8) {
        float4 f0, f1;
        if (i < U8) {
            f0 = __ldg(&ue[2 * i]);        f1 = __ldg(&ue[2 * i + 1]);
        } else {
            f0 = __ldg(&ie[2 * (i - U8)]); f1 = __ldg(&ie[2 * (i - U8) + 1]);
        }
        uint4 h;
        h.x = h2u(__float22half2_rn(make_float2(f0.x, f0.y)));
        h.y = h2u(__float22half2_rn(make_float2(f0.z, f0.w)));
        h.z = h2u(__float22half2_rn(make_float2(f1.x, f1.y)));
        h.w = h2u(__float22half2_rn(make_float2(f1.z, f1.w)));
        reinterpret_cast<uint4*>(g_h0)[i] = h;
    }

    // (2) perm build
    if (blk < NTILES) {
        int b = tid >> 2, q = tid & 3;
        int per = (blk + 3) >> 2;
        int p0 = q * per;
        int p1 = (blk < p0 + per) ? blk : p0 + per;
        int sum = 0;
        for (int p = p0; p < p1; p++) sum += __ldg(&g_bhist[p * NBUCKET + b]);
        sum += __shfl_xor_sync(0xffffffffu, sum, 1);
        sum += __shfl_xor_sync(0xffffffffu, sum, 2);
        if (q == 0) s_off[b] = __ldg(&g_dhist[b]) + sum;
        __syncthreads();
        int base = blk * SCAN_TILE + tid * 16;
        #pragma unroll
        for (int j = 0; j < 16; j++) {
            int idx = base + j;
            if (idx < NN) {
                int deg = __ldg(&g_rowptr[idx + 1]) - __ldg(&g_rowptr[idx]);
                int bb = deg < NBUCKET - 1 ? deg : NBUCKET - 1;
                int pos = atomicAdd(&s_off[bb], 1);
                g_perm[pos] = idx;
            }
        }
    }

    // (3) edge scatter
    if (i >= EE) return;
    int r = __ldcs(&rows[i]);
    int c = __ldcs(&cols[i]);
    float v = __ldcs(&vals[i]);
    int pos = atomicAdd(&g_cnt[r], 1);
    g_edges[pos] = make_int2(c, __float_as_int(v));
}

// ---------------------------------------------------------------------------
// CSR row accumulation core: simple loop, unroll 2. 8 threads/row, fp32 accum.
// ---------------------------------------------------------------------------
__device__ __forceinline__ void csr_accum(int row, int ch,
                                          const __half* __restrict__ src,
                                          float2& a0, float2& a1,
                                          float2& a2, float2& a3) {
    int e   = __ldg(&g_rowptr[row]);
    int end = __ldg(&g_rowptr[row + 1]);
    a0 = make_float2(0.f, 0.f); a1 = a0; a2 = a0; a3 = a0;
    #pragma unroll 2
    for (; e < end; e++) {
        int2 ev = __ldg(&g_edges[e]);
        float v = __int_as_float(ev.y);
        uint4 x = __ldg(reinterpret_cast<const uint4*>(src + (size_t)ev.x * DD + ch));
        float2 f0 = __half22float2(u2h(x.x));
        float2 f1 = __half22float2(u2h(x.y));
        float2 f2 = __half22float2(u2h(x.z));
        float2 f3 = __half22float2(u2h(x.w));
        a0.x += v * f0.x; a0.y += v * f0.y;
        a1.x += v * f1.x; a1.y += v * f1.y;
        a2.x += v * f2.x; a2.y += v * f2.y;
        a3.x += v * f3.x; a3.y += v * f3.y;
    }
}

// layers 1 & 2: store fp16. Epilogue restores invariants for the next call.
__global__ void __launch_bounds__(256) csr_spmm_kernel(const __half* __restrict__ src,
                                                       __half* __restrict__ dst) {
    int t = blockIdx.x * blockDim.x + threadIdx.x;
    if (t < NN) g_cnt[t] = 0;
    if (t < NTILES) g_tile_state[t] = 0ULL;
    if (t < NBUCKET) g_dhist[t] = 0;
    if (t < NTILES * NBUCKET) g_bhist[t] = 0;
    int rowIdx = t >> 3;
    if (rowIdx >= NN) return;
    int row = __ldg(&g_perm[rowIdx]);     // degree-sorted (heavy first)
    int ch = (t & 7) << 3;
    float2 a0, a1, a2, a3;
    csr_accum(row, ch, src, a0, a1, a2, a3);
    uint4 o;
    o.x = h2u(__float22half2_rn(a0));
    o.y = h2u(__float22half2_rn(a1));
    o.z = h2u(__float22half2_rn(a2));
    o.w = h2u(__float22half2_rn(a3));
    *reinterpret_cast<uint4*>(dst + (size_t)row * DD + ch) = o;
}

// layer 3 fused with final: out = (ego + h1 + h2 + h3)*0.25.
// ego/h1/h2 read from fp16 L2-resident buffers.
__global__ void __launch_bounds__(256) csr_spmm_final_kernel(float4* __restrict__ out) {
    int t = blockIdx.x * blockDim.x + threadIdx.x;
    int rowIdx = t >> 3;
    if (rowIdx >= NN) return;
    int row = __ldg(&g_perm[rowIdx]);
    int ch = (t & 7) << 3;
    float2 a0, a1, a2, a3;
    csr_accum(row, ch, g_bufB, a0, a1, a2, a3);   // h3 accum from h2

    size_t base = (size_t)row * DD + ch;
    uint4 ue0 = __ldg(reinterpret_cast<const uint4*>(g_h0   + base));
    uint4 uh1 = __ldg(reinterpret_cast<const uint4*>(g_bufA + base));
    uint4 uh2 = __ldg(reinterpret_cast<const uint4*>(g_bufB + base));
    float2 e00 = __half22float2(u2h(ue0.x)), e01 = __half22float2(u2h(ue0.y));
    float2 e02 = __half22float2(u2h(ue0.z)), e03 = __half22float2(u2h(ue0.w));
    float2 h10 = __half22float2(u2h(uh1.x)), h11 = __half22float2(u2h(uh1.y));
    float2 h12 = __half22float2(u2h(uh1.z)), h13 = __half22float2(u2h(uh1.w));
    float2 h20 = __half22float2(u2h(uh2.x)), h21 = __half22float2(u2h(uh2.y));
    float2 h22 = __half22float2(u2h(uh2.z)), h23 = __half22float2(u2h(uh2.w));

    float4 o0, o1;
    o0.x = (e00.x + h10.x + h20.x + a0.x) * 0.25f;
    o0.y = (e00.y + h10.y + h20.y + a0.y) * 0.25f;
    o0.z = (e01.x + h11.x + h21.x + a1.x) * 0.25f;
    o0.w = (e01.y + h11.y + h21.y + a1.y) * 0.25f;
    o1.x = (e02.x + h12.x + h22.x + a2.x) * 0.25f;
    o1.y = (e02.y + h12.y + h22.y + a2.y) * 0.25f;
    o1.z = (e03.x + h13.x + h23.x + a3.x) * 0.25f;
    o1.w = (e03.y + h13.y + h23.y + a3.y) * 0.25f;
    out[base / 4]     = o0;
    out[base / 4 + 1] = o1;
}

extern "C" void kernel_launch(void* const* d_in, const int* in_sizes, int n_in,
                              void* d_out, int out_size) {
    const float* user_emb = (const float*)d_in[0];
    const float* item_emb = (const float*)d_in[1];
    const int*   adj_rows = (const int*)d_in[2];
    const int*   adj_cols = (const int*)d_in[3];
    const float* adj_vals = (const float*)d_in[4];
    float* out = (float*)d_out;

    __half *h0, *bufA, *bufB;
    cudaGetSymbolAddress((void**)&h0,   g_h0);
    cudaGetSymbolAddress((void**)&bufA, g_bufA);
    cudaGetSymbolAddress((void**)&bufB, g_bufB);

    const int T = 256;
    const int EDGE_BLOCKS = (EE + T - 1) / T;          // 7813
    const int CS_BLOCKS   = (TOT8 + T - 1) / T;        // 9375 (covers EE too)
    const int SPMM_BLOCKS = (NN * 8 + T - 1) / T;

    hist_kernel<<<EDGE_BLOCKS, T>>>(adj_rows);
    scan_lookback_kernel<<<NTILES, T>>>();
    conv_scatter_kernel<<<CS_BLOCKS, T>>>((const float4*)user_emb,
                                          (const float4*)item_emb,
                                          adj_rows, adj_cols, adj_vals);

    csr_spmm_kernel<<<SPMM_BLOCKS, T>>>(h0,   bufA);
    csr_spmm_kernel<<<SPMM_BLOCKS, T>>>(bufA, bufB);
    csr_spmm_final_kernel<<<SPMM_BLOCKS, T>>>((float4*)out);
}